// round 1
// baseline (speedup 1.0000x reference)
#include <cuda_runtime.h>
#include <math.h>

// Problem constants
#define TT    2048
#define HH    4096
#define NHEAD 32
#define NKVH  8
#define HD    128
#define QSIZE 4096          // NHEAD*HD
#define KVSIZE 1024         // NKVH*HD
#define QKVW  6144          // QSIZE + 2*KVSIZE

// Scratch (no cudaMalloc allowed)
__device__ float g_qkv[(size_t)TT * QKVW];    // 50 MB
__device__ float g_attn[(size_t)TT * QSIZE];  // 32 MB

// ---------------------------------------------------------------------------
// Classic fp32 SGEMM: C[M,N] = A[M,K] @ B[K,N], all row-major.
// BM=BN=128, BK=8, 256 threads, 8x8 micro-tile. M,N % 128 == 0, K % 8 == 0.
// ---------------------------------------------------------------------------
__global__ __launch_bounds__(256) void sgemm128(const float* __restrict__ A,
                                                const float* __restrict__ B,
                                                float* __restrict__ C,
                                                int M, int N, int K) {
    __shared__ float As[8][128];
    __shared__ float Bs[8][128];

    const int tid = threadIdx.x;
    const int tx = tid & 15;
    const int ty = tid >> 4;
    const int bx = blockIdx.x;   // N tiles
    const int by = blockIdx.y;   // M tiles

    const int arow = tid >> 1;
    const int ac4  = (tid & 1) << 2;
    const int brow = tid >> 5;
    const int bc4  = (tid & 31) << 2;

    const float* Ap = A + (size_t)(by * 128 + arow) * K + ac4;
    const float* Bp = B + (size_t)brow * N + bx * 128 + bc4;

    float acc[8][8];
#pragma unroll
    for (int i = 0; i < 8; i++)
#pragma unroll
        for (int j = 0; j < 8; j++) acc[i][j] = 0.f;

    for (int k0 = 0; k0 < K; k0 += 8) {
        float4 a = *(const float4*)(Ap + k0);
        float4 b = *(const float4*)(Bp + (size_t)k0 * N);
        __syncthreads();
        As[ac4 + 0][arow] = a.x;
        As[ac4 + 1][arow] = a.y;
        As[ac4 + 2][arow] = a.z;
        As[ac4 + 3][arow] = a.w;
        *(float4*)&Bs[brow][bc4] = b;
        __syncthreads();
#pragma unroll
        for (int kk = 0; kk < 8; kk++) {
            float ar[8], br[8];
            *(float4*)(ar)     = *(const float4*)&As[kk][ty * 8];
            *(float4*)(ar + 4) = *(const float4*)&As[kk][ty * 8 + 4];
            *(float4*)(br)     = *(const float4*)&Bs[kk][tx * 8];
            *(float4*)(br + 4) = *(const float4*)&Bs[kk][tx * 8 + 4];
#pragma unroll
            for (int i = 0; i < 8; i++)
#pragma unroll
                for (int j = 0; j < 8; j++)
                    acc[i][j] = fmaf(ar[i], br[j], acc[i][j]);
        }
    }

#pragma unroll
    for (int i = 0; i < 8; i++) {
        float* cp = C + (size_t)(by * 128 + ty * 8 + i) * N + bx * 128 + tx * 8;
        *(float4*)(cp)     = make_float4(acc[i][0], acc[i][1], acc[i][2], acc[i][3]);
        *(float4*)(cp + 4) = make_float4(acc[i][4], acc[i][5], acc[i][6], acc[i][7]);
    }
}

// ---------------------------------------------------------------------------
// RoPE in-place on q (cols [0,4096)) and k (cols [4096,5120)) of g_qkv.
// One thread per (token, head, dim<64) rotation pair.
// ---------------------------------------------------------------------------
__global__ void rope_kernel(const int* __restrict__ pos, float* __restrict__ qkv) {
    const int total = TT * (NHEAD + NKVH) * 64;
    int idx = blockIdx.x * blockDim.x + threadIdx.x;
    if (idx >= total) return;
    int i = idx & 63;
    int h = (idx >> 6) % (NHEAD + NKVH);
    int t = idx / ((NHEAD + NKVH) * 64);
    int col = (h < NHEAD) ? h * HD : QSIZE + (h - NHEAD) * HD;
    float* p = qkv + (size_t)t * QKVW + col + i;
    double inv = pow(500000.0, -(double)i / 64.0);
    double fr = (double)pos[t] * inv;
    double s, c;
    sincos(fr, &s, &c);
    float cf = (float)c, sf = (float)s;
    float x1 = p[0], x2 = p[64];
    p[0]  = x1 * cf - x2 * sf;
    p[64] = x2 * cf + x1 * sf;
}

// ---------------------------------------------------------------------------
// Flash attention, fp32, causal, GQA (group=4).
// Block = (head, 64-query tile). 256 threads: tx in [0,16) owns 4 S-cols /
// 8 O-cols; ty in [0,16) owns 4 rows. Online softmax with shuffle reduce
// across the 16 tx lanes (lanes of same row sit in one 16-lane half-warp).
// ---------------------------------------------------------------------------
#define QS_STRIDE 129
#define KS_STRIDE 129
#define VS_STRIDE 128
#define PS_STRIDE 65
#define ATTN_SMEM ((64 * QS_STRIDE + 64 * KS_STRIDE + 64 * VS_STRIDE + 64 * PS_STRIDE) * 4)

__global__ __launch_bounds__(256) void attn_kernel(const float* __restrict__ qkv,
                                                   float* __restrict__ out) {
    extern __shared__ float sm[];
    float* Qs = sm;
    float* Ks = Qs + 64 * QS_STRIDE;
    float* Vs = Ks + 64 * KS_STRIDE;
    float* Ps = Vs + 64 * VS_STRIDE;

    const int h  = blockIdx.x;
    const int qb = blockIdx.y;
    const int kvh = h >> 2;
    const int tid = threadIdx.x;
    const int tx = tid & 15;
    const int ty = tid >> 4;
    const float scale = 0.08838834764831845f;  // 1/sqrt(128)

    // Load Q tile (pre-scaled)
    {
        const float* qp = qkv + (size_t)(qb * 64) * QKVW + h * HD;
        for (int i = tid; i < 64 * 32; i += 256) {
            int r = i >> 5, c = (i & 31) << 2;
            float4 v = *(const float4*)(qp + (size_t)r * QKVW + c);
            float* d = Qs + r * QS_STRIDE + c;
            d[0] = v.x * scale; d[1] = v.y * scale;
            d[2] = v.z * scale; d[3] = v.w * scale;
        }
    }

    float m_i[4], l_i[4], o[4][8];
#pragma unroll
    for (int r = 0; r < 4; r++) {
        m_i[r] = -INFINITY;
        l_i[r] = 0.f;
#pragma unroll
        for (int c = 0; c < 8; c++) o[r][c] = 0.f;
    }

    const int row0 = ty * 4;

    for (int j = 0; j <= qb; ++j) {
        __syncthreads();  // previous iteration's P@V done before K/V overwrite
        const float* kp = qkv + (size_t)(j * 64) * QKVW + QSIZE + kvh * HD;
        const float* vp = kp + KVSIZE;
        for (int i = tid; i < 64 * 32; i += 256) {
            int r = i >> 5, c = (i & 31) << 2;
            float4 k4 = *(const float4*)(kp + (size_t)r * QKVW + c);
            float* dk = Ks + r * KS_STRIDE + c;
            dk[0] = k4.x; dk[1] = k4.y; dk[2] = k4.z; dk[3] = k4.w;
            float4 v4 = *(const float4*)(vp + (size_t)r * QKVW + c);
            *(float4*)(Vs + r * VS_STRIDE + c) = v4;
        }
        __syncthreads();

        // S = (scaled Q) @ K^T  -> 4x4 per thread
        float s[4][4];
#pragma unroll
        for (int r = 0; r < 4; r++)
#pragma unroll
            for (int c = 0; c < 4; c++) s[r][c] = 0.f;

#pragma unroll 4
        for (int k = 0; k < HD; k++) {
            float qv[4], kv[4];
#pragma unroll
            for (int r = 0; r < 4; r++) qv[r] = Qs[(row0 + r) * QS_STRIDE + k];
#pragma unroll
            for (int c = 0; c < 4; c++) kv[c] = Ks[(tx * 4 + c) * KS_STRIDE + k];
#pragma unroll
            for (int r = 0; r < 4; r++)
#pragma unroll
                for (int c = 0; c < 4; c++)
                    s[r][c] = fmaf(qv[r], kv[c], s[r][c]);
        }

        if (j == qb) {  // causal mask on diagonal block
#pragma unroll
            for (int r = 0; r < 4; r++) {
                int gr = row0 + r;
#pragma unroll
                for (int c = 0; c < 4; c++)
                    if (tx * 4 + c > gr) s[r][c] = -INFINITY;
            }
        }

        // Online softmax per row
#pragma unroll
        for (int r = 0; r < 4; r++) {
            float mx = fmaxf(fmaxf(s[r][0], s[r][1]), fmaxf(s[r][2], s[r][3]));
#pragma unroll
            for (int off = 1; off < 16; off <<= 1)
                mx = fmaxf(mx, __shfl_xor_sync(0xffffffffu, mx, off));
            float mnew = fmaxf(m_i[r], mx);
            float corr = __expf(m_i[r] - mnew);
            m_i[r] = mnew;
            float rs = 0.f;
#pragma unroll
            for (int c = 0; c < 4; c++) {
                float p = __expf(s[r][c] - mnew);
                s[r][c] = p;
                rs += p;
            }
#pragma unroll
            for (int off = 1; off < 16; off <<= 1)
                rs += __shfl_xor_sync(0xffffffffu, rs, off);
            l_i[r] = l_i[r] * corr + rs;
#pragma unroll
            for (int c = 0; c < 8; c++) o[r][c] *= corr;
#pragma unroll
            for (int c = 0; c < 4; c++)
                Ps[(row0 + r) * PS_STRIDE + tx * 4 + c] = s[r][c];
        }
        __syncthreads();

        // O += P @ V   (thread owns rows row0..+3, cols tx*8..+7)
#pragma unroll 2
        for (int sI = 0; sI < 64; sI++) {
            float4 v0 = *(const float4*)(Vs + sI * VS_STRIDE + tx * 8);
            float4 v1 = *(const float4*)(Vs + sI * VS_STRIDE + tx * 8 + 4);
#pragma unroll
            for (int r = 0; r < 4; r++) {
                float p = Ps[(row0 + r) * PS_STRIDE + sI];
                o[r][0] = fmaf(p, v0.x, o[r][0]);
                o[r][1] = fmaf(p, v0.y, o[r][1]);
                o[r][2] = fmaf(p, v0.z, o[r][2]);
                o[r][3] = fmaf(p, v0.w, o[r][3]);
                o[r][4] = fmaf(p, v1.x, o[r][4]);
                o[r][5] = fmaf(p, v1.y, o[r][5]);
                o[r][6] = fmaf(p, v1.z, o[r][6]);
                o[r][7] = fmaf(p, v1.w, o[r][7]);
            }
        }
    }

    // Normalize and write O as (T, NHEAD*HD)
#pragma unroll
    for (int r = 0; r < 4; r++) {
        float inv = 1.f / l_i[r];
        float* op = out + (size_t)(qb * 64 + row0 + r) * QSIZE + h * HD + tx * 8;
#pragma unroll
        for (int c = 0; c < 8; c++) op[c] = o[r][c] * inv;
    }
}

// ---------------------------------------------------------------------------
extern "C" void kernel_launch(void* const* d_in, const int* in_sizes, int n_in,
                              void* d_out, int out_size) {
    const int*   positions = (const int*)d_in[0];
    const float* hidden    = (const float*)d_in[1];
    const float* w_qkv     = (const float*)d_in[2];
    const float* w_o       = (const float*)d_in[3];
    float*       out       = (float*)d_out;

    void *qkv_p, *attn_p;
    cudaGetSymbolAddress(&qkv_p, g_qkv);
    cudaGetSymbolAddress(&attn_p, g_attn);
    float* qkv  = (float*)qkv_p;
    float* attn = (float*)attn_p;

    cudaFuncSetAttribute(attn_kernel, cudaFuncAttributeMaxDynamicSharedMemorySize,
                         ATTN_SMEM);

    // 1) qkv = hidden @ w_qkv   (2048x4096 @ 4096x6144)
    {
        dim3 grid(QKVW / 128, TT / 128);
        sgemm128<<<grid, 256>>>(hidden, w_qkv, qkv, TT, QKVW, HH);
    }
    // 2) RoPE on q,k
    {
        int total = TT * (NHEAD + NKVH) * 64;
        rope_kernel<<<(total + 255) / 256, 256>>>(positions, qkv);
    }
    // 3) attention
    {
        dim3 grid(NHEAD, TT / 64);
        attn_kernel<<<grid, 256, ATTN_SMEM>>>(qkv, attn);
    }
    // 4) out = attn @ w_o       (2048x4096 @ 4096x4096)
    {
        dim3 grid(HH / 128, TT / 128);
        sgemm128<<<grid, 256>>>(attn, w_o, out, TT, HH, QSIZE);
    }
}

// round 2
// speedup vs baseline: 1.3574x; 1.3574x over previous
#include <cuda_runtime.h>
#include <math.h>
#include <stdint.h>

// Problem constants
#define TT    2048
#define HH    4096
#define NHEAD 32
#define NKVH  8
#define HD    128
#define QSIZE 4096          // NHEAD*HD
#define KVSIZE 1024         // NKVH*HD
#define QKVW  6144          // QSIZE + 2*KVSIZE

// Scratch (no cudaMalloc allowed)
__device__ float g_qkv[(size_t)TT * QKVW];    // 50 MB
__device__ float g_attn[(size_t)TT * QSIZE];  // 32 MB

// ---------------------------------------------------------------------------
// TF32 tensor-core GEMM: C[M,N] = A[M,K] @ B[K,N], row-major.
// 128x128x16 CTA tile, 256 threads = 8 warps (2x4), warp tile 64x32.
// mma.sync.m16n8k8.tf32, ldmatrix.x4 fragment loads, double-buffered smem.
// Requires M%128==0, N%128==0, K%16==0.
// ---------------------------------------------------------------------------
#define BM 128
#define BN 128
#define BK 16
#define ASTR 20   // floats per A row in smem (pad for conflict-free ldmatrix)
#define BSTR 20

__device__ __forceinline__ float f2tf32(float x) {
    uint32_t u;
    asm("cvt.rna.tf32.f32 %0, %1;" : "=r"(u) : "f"(x));
    return __uint_as_float(u);
}

__device__ __forceinline__ uint32_t smem_u32(const void* p) {
    return (uint32_t)__cvta_generic_to_shared(p);
}

__device__ __forceinline__ void ldsm4(uint32_t& r0, uint32_t& r1, uint32_t& r2,
                                      uint32_t& r3, uint32_t addr) {
    asm volatile("ldmatrix.sync.aligned.m8n8.x4.shared.b16 {%0,%1,%2,%3}, [%4];"
                 : "=r"(r0), "=r"(r1), "=r"(r2), "=r"(r3) : "r"(addr));
}

__device__ __forceinline__ void mma_tf32(float c[4], uint32_t a0, uint32_t a1,
                                         uint32_t a2, uint32_t a3,
                                         uint32_t b0, uint32_t b1) {
    asm volatile(
        "mma.sync.aligned.m16n8k8.row.col.f32.tf32.tf32.f32 "
        "{%0,%1,%2,%3}, {%4,%5,%6,%7}, {%8,%9}, {%0,%1,%2,%3};"
        : "+f"(c[0]), "+f"(c[1]), "+f"(c[2]), "+f"(c[3])
        : "r"(a0), "r"(a1), "r"(a2), "r"(a3), "r"(b0), "r"(b1));
}

__global__ __launch_bounds__(256) void tgemm(const float* __restrict__ A,
                                             const float* __restrict__ B,
                                             float* __restrict__ C,
                                             int M, int N, int K) {
    __shared__ float As[2][BM][ASTR];   // row-major [m][k]
    __shared__ float Bs[2][BN][BSTR];   // transposed [n][k]

    const int tid  = threadIdx.x;
    const int lane = tid & 31;
    const int wid  = tid >> 5;
    const int mwarp = (wid >> 2) * 64;  // 0 or 64
    const int nwarp = (wid & 3) * 32;   // 0,32,64,96
    const int bx = blockIdx.x, by = blockIdx.y;

    // global load mapping: 2 float4 per thread for each of A,B
    const int f0   = tid * 2;
    const int arow = f0 >> 2;           // 0..127
    const int akc  = (f0 & 3) * 4;      // 0 or 8
    const int brow = f0 >> 5;           // 0..15 (k)
    const int bcol = (f0 & 31) * 4;     // 0..120 step 8 (n)

    const float* Aptr = A + (size_t)(by * BM + arow) * K + akc;
    const float* Bptr = B + (size_t)brow * N + bx * BN + bcol;

    float4 aR0, aR1, bR0, bR1;
    aR0 = *(const float4*)(Aptr);
    aR1 = *(const float4*)(Aptr + 4);
    bR0 = *(const float4*)(Bptr);
    bR1 = *(const float4*)(Bptr + 4);

    float acc[4][4][4];
#pragma unroll
    for (int mi = 0; mi < 4; mi++)
#pragma unroll
        for (int ni = 0; ni < 4; ni++)
#pragma unroll
            for (int r = 0; r < 4; r++) acc[mi][ni][r] = 0.f;

    // store helpers (tf32 conversion on the way in)
#define STORE_A(buf)                                                  \
    {                                                                 \
        float* d = &As[buf][arow][akc];                               \
        d[0] = f2tf32(aR0.x); d[1] = f2tf32(aR0.y);                   \
        d[2] = f2tf32(aR0.z); d[3] = f2tf32(aR0.w);                   \
        d[4] = f2tf32(aR1.x); d[5] = f2tf32(aR1.y);                   \
        d[6] = f2tf32(aR1.z); d[7] = f2tf32(aR1.w);                   \
    }
#define STORE_B(buf)                                                  \
    {                                                                 \
        Bs[buf][bcol + 0][brow] = f2tf32(bR0.x);                      \
        Bs[buf][bcol + 1][brow] = f2tf32(bR0.y);                      \
        Bs[buf][bcol + 2][brow] = f2tf32(bR0.z);                      \
        Bs[buf][bcol + 3][brow] = f2tf32(bR0.w);                      \
        Bs[buf][bcol + 4][brow] = f2tf32(bR1.x);                      \
        Bs[buf][bcol + 5][brow] = f2tf32(bR1.y);                      \
        Bs[buf][bcol + 6][brow] = f2tf32(bR1.z);                      \
        Bs[buf][bcol + 7][brow] = f2tf32(bR1.w);                      \
    }

    STORE_A(0);
    STORE_B(0);
    __syncthreads();

    // ldmatrix per-lane base addresses
    // A frag: row = mwarp + mi*16 + (lane&15), kcol = ks*8 + (lane>>4)*4
    const uint32_t aAddr =
        smem_u32(&As[0][mwarp + (lane & 15)][(lane >> 4) * 4]);
    // B frag: n = nwarp + ni*8 + (lane&7), kcol = (lane>>3)*4
    const uint32_t bAddr =
        smem_u32(&Bs[0][nwarp + (lane & 7)][(lane >> 3) * 4]);
    const uint32_t bufAbytes = BM * ASTR * 4;
    const uint32_t bufBbytes = BN * BSTR * 4;

    const int KT = K / BK;
    for (int kt = 0; kt < KT; kt++) {
        const int cur = kt & 1;
        if (kt + 1 < KT) {
            const float* An = Aptr + (kt + 1) * BK;
            const float* Bn = Bptr + (size_t)(kt + 1) * BK * N;
            aR0 = *(const float4*)(An);
            aR1 = *(const float4*)(An + 4);
            bR0 = *(const float4*)(Bn);
            bR1 = *(const float4*)(Bn + 4);
        }

        const uint32_t aBase = aAddr + cur * bufAbytes;
        const uint32_t bBase = bAddr + cur * bufBbytes;

        uint32_t bF[4][4];
#pragma unroll
        for (int ni = 0; ni < 4; ni++)
            ldsm4(bF[ni][0], bF[ni][1], bF[ni][2], bF[ni][3],
                  bBase + ni * 8 * BSTR * 4);

#pragma unroll
        for (int ks = 0; ks < 2; ks++) {
            uint32_t aF[4][4];
#pragma unroll
            for (int mi = 0; mi < 4; mi++)
                ldsm4(aF[mi][0], aF[mi][1], aF[mi][2], aF[mi][3],
                      aBase + mi * 16 * ASTR * 4 + ks * 32);
#pragma unroll
            for (int mi = 0; mi < 4; mi++)
#pragma unroll
                for (int ni = 0; ni < 4; ni++)
                    mma_tf32(acc[mi][ni], aF[mi][0], aF[mi][1], aF[mi][2],
                             aF[mi][3], bF[ni][ks * 2], bF[ni][ks * 2 + 1]);
        }

        if (kt + 1 < KT) {
            __syncthreads();
            STORE_A(cur ^ 1);
            STORE_B(cur ^ 1);
            __syncthreads();
        }
    }

    // epilogue
#pragma unroll
    for (int mi = 0; mi < 4; mi++) {
#pragma unroll
        for (int ni = 0; ni < 4; ni++) {
            int r = by * BM + mwarp + mi * 16 + (lane >> 2);
            int c = bx * BN + nwarp + ni * 8 + (lane & 3) * 2;
            *(float2*)&C[(size_t)r * N + c] =
                make_float2(acc[mi][ni][0], acc[mi][ni][1]);
            *(float2*)&C[(size_t)(r + 8) * N + c] =
                make_float2(acc[mi][ni][2], acc[mi][ni][3]);
        }
    }
#undef STORE_A
#undef STORE_B
}

// ---------------------------------------------------------------------------
// RoPE in-place on q (cols [0,4096)) and k (cols [4096,5120)) of g_qkv.
// ---------------------------------------------------------------------------
__global__ void rope_kernel(const int* __restrict__ pos, float* __restrict__ qkv) {
    const int total = TT * (NHEAD + NKVH) * 64;
    int idx = blockIdx.x * blockDim.x + threadIdx.x;
    if (idx >= total) return;
    int i = idx & 63;
    int h = (idx >> 6) % (NHEAD + NKVH);
    int t = idx / ((NHEAD + NKVH) * 64);
    int col = (h < NHEAD) ? h * HD : QSIZE + (h - NHEAD) * HD;
    float* p = qkv + (size_t)t * QKVW + col + i;
    double inv = pow(500000.0, -(double)i / 64.0);
    double fr = (double)pos[t] * inv;
    double s, c;
    sincos(fr, &s, &c);
    float cf = (float)c, sf = (float)s;
    float x1 = p[0], x2 = p[64];
    p[0]  = x1 * cf - x2 * sf;
    p[64] = x2 * cf + x1 * sf;
}

// ---------------------------------------------------------------------------
// Flash attention, fp32, causal, GQA (group=4). (unchanged from R1)
// ---------------------------------------------------------------------------
#define QS_STRIDE 129
#define KS_STRIDE 129
#define VS_STRIDE 128
#define PS_STRIDE 65
#define ATTN_SMEM ((64 * QS_STRIDE + 64 * KS_STRIDE + 64 * VS_STRIDE + 64 * PS_STRIDE) * 4)

__global__ __launch_bounds__(256) void attn_kernel(const float* __restrict__ qkv,
                                                   float* __restrict__ out) {
    extern __shared__ float sm[];
    float* Qs = sm;
    float* Ks = Qs + 64 * QS_STRIDE;
    float* Vs = Ks + 64 * KS_STRIDE;
    float* Ps = Vs + 64 * VS_STRIDE;

    const int h  = blockIdx.x;
    const int qb = blockIdx.y;
    const int kvh = h >> 2;
    const int tid = threadIdx.x;
    const int tx = tid & 15;
    const int ty = tid >> 4;
    const float scale = 0.08838834764831845f;  // 1/sqrt(128)

    {
        const float* qp = qkv + (size_t)(qb * 64) * QKVW + h * HD;
        for (int i = tid; i < 64 * 32; i += 256) {
            int r = i >> 5, c = (i & 31) << 2;
            float4 v = *(const float4*)(qp + (size_t)r * QKVW + c);
            float* d = Qs + r * QS_STRIDE + c;
            d[0] = v.x * scale; d[1] = v.y * scale;
            d[2] = v.z * scale; d[3] = v.w * scale;
        }
    }

    float m_i[4], l_i[4], o[4][8];
#pragma unroll
    for (int r = 0; r < 4; r++) {
        m_i[r] = -INFINITY;
        l_i[r] = 0.f;
#pragma unroll
        for (int c = 0; c < 8; c++) o[r][c] = 0.f;
    }

    const int row0 = ty * 4;

    for (int j = 0; j <= qb; ++j) {
        __syncthreads();
        const float* kp = qkv + (size_t)(j * 64) * QKVW + QSIZE + kvh * HD;
        const float* vp = kp + KVSIZE;
        for (int i = tid; i < 64 * 32; i += 256) {
            int r = i >> 5, c = (i & 31) << 2;
            float4 k4 = *(const float4*)(kp + (size_t)r * QKVW + c);
            float* dk = Ks + r * KS_STRIDE + c;
            dk[0] = k4.x; dk[1] = k4.y; dk[2] = k4.z; dk[3] = k4.w;
            float4 v4 = *(const float4*)(vp + (size_t)r * QKVW + c);
            *(float4*)(Vs + r * VS_STRIDE + c) = v4;
        }
        __syncthreads();

        float s[4][4];
#pragma unroll
        for (int r = 0; r < 4; r++)
#pragma unroll
            for (int c = 0; c < 4; c++) s[r][c] = 0.f;

#pragma unroll 4
        for (int k = 0; k < HD; k++) {
            float qv[4], kv[4];
#pragma unroll
            for (int r = 0; r < 4; r++) qv[r] = Qs[(row0 + r) * QS_STRIDE + k];
#pragma unroll
            for (int c = 0; c < 4; c++) kv[c] = Ks[(tx * 4 + c) * KS_STRIDE + k];
#pragma unroll
            for (int r = 0; r < 4; r++)
#pragma unroll
                for (int c = 0; c < 4; c++)
                    s[r][c] = fmaf(qv[r], kv[c], s[r][c]);
        }

        if (j == qb) {
#pragma unroll
            for (int r = 0; r < 4; r++) {
                int gr = row0 + r;
#pragma unroll
                for (int c = 0; c < 4; c++)
                    if (tx * 4 + c > gr) s[r][c] = -INFINITY;
            }
        }

#pragma unroll
        for (int r = 0; r < 4; r++) {
            float mx = fmaxf(fmaxf(s[r][0], s[r][1]), fmaxf(s[r][2], s[r][3]));
#pragma unroll
            for (int off = 1; off < 16; off <<= 1)
                mx = fmaxf(mx, __shfl_xor_sync(0xffffffffu, mx, off));
            float mnew = fmaxf(m_i[r], mx);
            float corr = __expf(m_i[r] - mnew);
            m_i[r] = mnew;
            float rs = 0.f;
#pragma unroll
            for (int c = 0; c < 4; c++) {
                float p = __expf(s[r][c] - mnew);
                s[r][c] = p;
                rs += p;
            }
#pragma unroll
            for (int off = 1; off < 16; off <<= 1)
                rs += __shfl_xor_sync(0xffffffffu, rs, off);
            l_i[r] = l_i[r] * corr + rs;
#pragma unroll
            for (int c = 0; c < 8; c++) o[r][c] *= corr;
#pragma unroll
            for (int c = 0; c < 4; c++)
                Ps[(row0 + r) * PS_STRIDE + tx * 4 + c] = s[r][c];
        }
        __syncthreads();

#pragma unroll 2
        for (int sI = 0; sI < 64; sI++) {
            float4 v0 = *(const float4*)(Vs + sI * VS_STRIDE + tx * 8);
            float4 v1 = *(const float4*)(Vs + sI * VS_STRIDE + tx * 8 + 4);
#pragma unroll
            for (int r = 0; r < 4; r++) {
                float p = Ps[(row0 + r) * PS_STRIDE + sI];
                o[r][0] = fmaf(p, v0.x, o[r][0]);
                o[r][1] = fmaf(p, v0.y, o[r][1]);
                o[r][2] = fmaf(p, v0.z, o[r][2]);
                o[r][3] = fmaf(p, v0.w, o[r][3]);
                o[r][4] = fmaf(p, v1.x, o[r][4]);
                o[r][5] = fmaf(p, v1.y, o[r][5]);
                o[r][6] = fmaf(p, v1.z, o[r][6]);
                o[r][7] = fmaf(p, v1.w, o[r][7]);
            }
        }
    }

#pragma unroll
    for (int r = 0; r < 4; r++) {
        float inv = 1.f / l_i[r];
        float* op = out + (size_t)(qb * 64 + row0 + r) * QSIZE + h * HD + tx * 8;
#pragma unroll
        for (int c = 0; c < 8; c++) op[c] = o[r][c] * inv;
    }
}

// ---------------------------------------------------------------------------
extern "C" void kernel_launch(void* const* d_in, const int* in_sizes, int n_in,
                              void* d_out, int out_size) {
    const int*   positions = (const int*)d_in[0];
    const float* hidden    = (const float*)d_in[1];
    const float* w_qkv     = (const float*)d_in[2];
    const float* w_o       = (const float*)d_in[3];
    float*       out       = (float*)d_out;

    void *qkv_p, *attn_p;
    cudaGetSymbolAddress(&qkv_p, g_qkv);
    cudaGetSymbolAddress(&attn_p, g_attn);
    float* qkv  = (float*)qkv_p;
    float* attn = (float*)attn_p;

    cudaFuncSetAttribute(attn_kernel, cudaFuncAttributeMaxDynamicSharedMemorySize,
                         ATTN_SMEM);

    // 1) qkv = hidden @ w_qkv   (2048x4096 @ 4096x6144), tf32 tensor cores
    {
        dim3 grid(QKVW / BN, TT / BM);
        tgemm<<<grid, 256>>>(hidden, w_qkv, qkv, TT, QKVW, HH);
    }
    // 2) RoPE on q,k
    {
        int total = TT * (NHEAD + NKVH) * 64;
        rope_kernel<<<(total + 255) / 256, 256>>>(positions, qkv);
    }
    // 3) attention (fp32 flash)
    {
        dim3 grid(NHEAD, TT / 64);
        attn_kernel<<<grid, 256, ATTN_SMEM>>>(qkv, attn);
    }
    // 4) out = attn @ w_o       (2048x4096 @ 4096x4096), tf32 tensor cores
    {
        dim3 grid(HH / BN, TT / BM);
        tgemm<<<grid, 256>>>(attn, w_o, out, TT, HH, QSIZE);
    }
}

// round 3
// speedup vs baseline: 2.3760x; 1.7504x over previous
#include <cuda_runtime.h>
#include <math.h>
#include <stdint.h>

// Problem constants
#define TT    2048
#define HH    4096
#define NHEAD 32
#define NKVH  8
#define HD    128
#define QSIZE 4096          // NHEAD*HD
#define KVSIZE 1024         // NKVH*HD
#define QKVW  6144          // QSIZE + 2*KVSIZE

// Scratch (no cudaMalloc allowed)
__device__ float g_qkv[(size_t)TT * QKVW];    // 50 MB
__device__ float g_attn[(size_t)TT * QSIZE];  // 32 MB

// ---------------------------------------------------------------------------
// Common tensor-core helpers (mma.m16n8k8.tf32)
// ---------------------------------------------------------------------------
__device__ __forceinline__ float f2tf32(float x) {
    uint32_t u;
    asm("cvt.rna.tf32.f32 %0, %1;" : "=r"(u) : "f"(x));
    return __uint_as_float(u);
}

__device__ __forceinline__ uint32_t smem_u32(const void* p) {
    return (uint32_t)__cvta_generic_to_shared(p);
}

__device__ __forceinline__ void ldsm4(uint32_t& r0, uint32_t& r1, uint32_t& r2,
                                      uint32_t& r3, uint32_t addr) {
    asm volatile("ldmatrix.sync.aligned.m8n8.x4.shared.b16 {%0,%1,%2,%3}, [%4];"
                 : "=r"(r0), "=r"(r1), "=r"(r2), "=r"(r3) : "r"(addr));
}

__device__ __forceinline__ void mma_tf32(float c[4], uint32_t a0, uint32_t a1,
                                         uint32_t a2, uint32_t a3,
                                         uint32_t b0, uint32_t b1) {
    asm volatile(
        "mma.sync.aligned.m16n8k8.row.col.f32.tf32.tf32.f32 "
        "{%0,%1,%2,%3}, {%4,%5,%6,%7}, {%8,%9}, {%0,%1,%2,%3};"
        : "+f"(c[0]), "+f"(c[1]), "+f"(c[2]), "+f"(c[3])
        : "r"(a0), "r"(a1), "r"(a2), "r"(a3), "r"(b0), "r"(b1));
}

// ---------------------------------------------------------------------------
// TF32 tensor-core GEMM: C[M,N] = A[M,K] @ B[K,N], row-major. (unchanged R2)
// ---------------------------------------------------------------------------
#define BM 128
#define BN 128
#define BK 16
#define ASTR 20
#define BSTR 20

__global__ __launch_bounds__(256) void tgemm(const float* __restrict__ A,
                                             const float* __restrict__ B,
                                             float* __restrict__ C,
                                             int M, int N, int K) {
    __shared__ float As[2][BM][ASTR];
    __shared__ float Bs[2][BN][BSTR];

    const int tid  = threadIdx.x;
    const int lane = tid & 31;
    const int wid  = tid >> 5;
    const int mwarp = (wid >> 2) * 64;
    const int nwarp = (wid & 3) * 32;
    const int bx = blockIdx.x, by = blockIdx.y;

    const int f0   = tid * 2;
    const int arow = f0 >> 2;
    const int akc  = (f0 & 3) * 4;
    const int brow = f0 >> 5;
    const int bcol = (f0 & 31) * 4;

    const float* Aptr = A + (size_t)(by * BM + arow) * K + akc;
    const float* Bptr = B + (size_t)brow * N + bx * BN + bcol;

    float4 aR0, aR1, bR0, bR1;
    aR0 = *(const float4*)(Aptr);
    aR1 = *(const float4*)(Aptr + 4);
    bR0 = *(const float4*)(Bptr);
    bR1 = *(const float4*)(Bptr + 4);

    float acc[4][4][4];
#pragma unroll
    for (int mi = 0; mi < 4; mi++)
#pragma unroll
        for (int ni = 0; ni < 4; ni++)
#pragma unroll
            for (int r = 0; r < 4; r++) acc[mi][ni][r] = 0.f;

#define STORE_A(buf)                                                  \
    {                                                                 \
        float* d = &As[buf][arow][akc];                               \
        d[0] = f2tf32(aR0.x); d[1] = f2tf32(aR0.y);                   \
        d[2] = f2tf32(aR0.z); d[3] = f2tf32(aR0.w);                   \
        d[4] = f2tf32(aR1.x); d[5] = f2tf32(aR1.y);                   \
        d[6] = f2tf32(aR1.z); d[7] = f2tf32(aR1.w);                   \
    }
#define STORE_B(buf)                                                  \
    {                                                                 \
        Bs[buf][bcol + 0][brow] = f2tf32(bR0.x);                      \
        Bs[buf][bcol + 1][brow] = f2tf32(bR0.y);                      \
        Bs[buf][bcol + 2][brow] = f2tf32(bR0.z);                      \
        Bs[buf][bcol + 3][brow] = f2tf32(bR0.w);                      \
        Bs[buf][bcol + 4][brow] = f2tf32(bR1.x);                      \
        Bs[buf][bcol + 5][brow] = f2tf32(bR1.y);                      \
        Bs[buf][bcol + 6][brow] = f2tf32(bR1.z);                      \
        Bs[buf][bcol + 7][brow] = f2tf32(bR1.w);                      \
    }

    STORE_A(0);
    STORE_B(0);
    __syncthreads();

    const uint32_t aAddr =
        smem_u32(&As[0][mwarp + (lane & 15)][(lane >> 4) * 4]);
    const uint32_t bAddr =
        smem_u32(&Bs[0][nwarp + (lane & 7)][(lane >> 3) * 4]);
    const uint32_t bufAbytes = BM * ASTR * 4;
    const uint32_t bufBbytes = BN * BSTR * 4;

    const int KT = K / BK;
    for (int kt = 0; kt < KT; kt++) {
        const int cur = kt & 1;
        if (kt + 1 < KT) {
            const float* An = Aptr + (kt + 1) * BK;
            const float* Bn = Bptr + (size_t)(kt + 1) * BK * N;
            aR0 = *(const float4*)(An);
            aR1 = *(const float4*)(An + 4);
            bR0 = *(const float4*)(Bn);
            bR1 = *(const float4*)(Bn + 4);
        }

        const uint32_t aBase = aAddr + cur * bufAbytes;
        const uint32_t bBase = bAddr + cur * bufBbytes;

        uint32_t bF[4][4];
#pragma unroll
        for (int ni = 0; ni < 4; ni++)
            ldsm4(bF[ni][0], bF[ni][1], bF[ni][2], bF[ni][3],
                  bBase + ni * 8 * BSTR * 4);

#pragma unroll
        for (int ks = 0; ks < 2; ks++) {
            uint32_t aF[4][4];
#pragma unroll
            for (int mi = 0; mi < 4; mi++)
                ldsm4(aF[mi][0], aF[mi][1], aF[mi][2], aF[mi][3],
                      aBase + mi * 16 * ASTR * 4 + ks * 32);
#pragma unroll
            for (int mi = 0; mi < 4; mi++)
#pragma unroll
                for (int ni = 0; ni < 4; ni++)
                    mma_tf32(acc[mi][ni], aF[mi][0], aF[mi][1], aF[mi][2],
                             aF[mi][3], bF[ni][ks * 2], bF[ni][ks * 2 + 1]);
        }

        if (kt + 1 < KT) {
            __syncthreads();
            STORE_A(cur ^ 1);
            STORE_B(cur ^ 1);
            __syncthreads();
        }
    }

#pragma unroll
    for (int mi = 0; mi < 4; mi++) {
#pragma unroll
        for (int ni = 0; ni < 4; ni++) {
            int r = by * BM + mwarp + mi * 16 + (lane >> 2);
            int c = bx * BN + nwarp + ni * 8 + (lane & 3) * 2;
            *(float2*)&C[(size_t)r * N + c] =
                make_float2(acc[mi][ni][0], acc[mi][ni][1]);
            *(float2*)&C[(size_t)(r + 8) * N + c] =
                make_float2(acc[mi][ni][2], acc[mi][ni][3]);
        }
    }
#undef STORE_A
#undef STORE_B
}

// ---------------------------------------------------------------------------
// RoPE in-place, fp32 math (matches fp32 reference; avoids slow FP64 pipe)
// ---------------------------------------------------------------------------
__global__ void rope_kernel(const int* __restrict__ pos, float* __restrict__ qkv) {
    const int total = TT * (NHEAD + NKVH) * 64;
    int idx = blockIdx.x * blockDim.x + threadIdx.x;
    if (idx >= total) return;
    int i = idx & 63;
    int h = (idx >> 6) % (NHEAD + NKVH);
    int t = idx / ((NHEAD + NKVH) * 64);
    int col = (h < NHEAD) ? h * HD : QSIZE + (h - NHEAD) * HD;
    float* p = qkv + (size_t)t * QKVW + col + i;
    // inv_freq = 500000^(-i/64) = exp2(-i * log2(500000)/64)
    float inv = exp2f(-(float)i * 0.2958057710522857f);
    float fr = (float)pos[t] * inv;
    float s, c;
    sincosf(fr, &s, &c);
    float x1 = p[0], x2 = p[64];
    p[0]  = x1 * c - x2 * s;
    p[64] = x2 * c + x1 * s;
}

// ---------------------------------------------------------------------------
// Tensor-core flash attention (tf32), causal, GQA group=4.
// CTA = (head, 128-query block). 8 warps x 16 q-rows. KV tile = 64.
// Q,K natural [row][d] layouts feed ldmatrix A/B operands directly.
// V natural [s][d]; B-fragments via conflict-free direct LDS (VSTR=136).
// P per-warp-private smem strip -> only __syncwarp around it.
// ---------------------------------------------------------------------------
#define ABQ  128
#define ABKV 64
#define QSTR 132
#define KSTR 132
#define VSTR 136
#define PSTR 68
#define ATT_SMEM ((ABQ * QSTR + ABKV * KSTR + ABKV * VSTR + ABQ * PSTR) * 4)

__global__ __launch_bounds__(256) void attn_tc(const float* __restrict__ qkv,
                                               float* __restrict__ out) {
    extern __shared__ float sm[];
    float* Qs = sm;                       // [128][QSTR]
    float* Ks = Qs + ABQ * QSTR;          // [64][KSTR]
    float* Vs = Ks + ABKV * KSTR;         // [64][VSTR]
    float* Ps = Vs + ABKV * VSTR;         // [128][PSTR]

    const int h  = blockIdx.x;
    const int qb = gridDim.y - 1 - blockIdx.y;   // heavy tiles first
    const int kvh = h >> 2;
    const int tid = threadIdx.x;
    const int lane = tid & 31;
    const int wid = tid >> 5;
    const int q0 = wid * 16;
    // softmax in base-2: fold scale * log2(e) into Q
    const float qsc = 0.08838834764831845f * 1.4426950408889634f;

    // ---- load Q tile (pre-scaled, tf32-rounded) ----
    {
        const float* qp = qkv + (size_t)(qb * ABQ) * QKVW + h * HD;
        for (int i = tid; i < ABQ * 32; i += 256) {
            int r = i >> 5, c = (i & 31) * 4;
            float4 v = *(const float4*)(qp + (size_t)r * QKVW + c);
            v.x = f2tf32(v.x * qsc); v.y = f2tf32(v.y * qsc);
            v.z = f2tf32(v.z * qsc); v.w = f2tf32(v.w * qsc);
            *(float4*)(Qs + r * QSTR + c) = v;
        }
    }

    float m0 = -1e30f, m1 = -1e30f, l0 = 0.f, l1 = 0.f;
    float o[16][4];
#pragma unroll
    for (int ni = 0; ni < 16; ni++)
#pragma unroll
        for (int r = 0; r < 4; r++) o[ni][r] = 0.f;

    const uint32_t qA = smem_u32(&Qs[(q0 + (lane & 15)) * QSTR + (lane >> 4) * 4]);
    const uint32_t kB = smem_u32(&Ks[(lane & 7) * KSTR + (lane >> 3) * 4]);
    const uint32_t pA = smem_u32(&Ps[(q0 + (lane & 15)) * PSTR + (lane >> 4) * 4]);

    const int rowg0 = qb * ABQ + q0;     // warp's first global q row
    const int jmax = qb * 2 + 1;

    for (int j = 0; j <= jmax; j++) {
        __syncthreads();   // previous iteration's reads of Ks/Vs complete
        {
            const float* kp = qkv + (size_t)(j * ABKV) * QKVW + QSIZE + kvh * HD;
            const float* vp = kp + KVSIZE;
            for (int i = tid; i < ABKV * 32; i += 256) {
                int r = i >> 5, c = (i & 31) * 4;
                float4 kk = *(const float4*)(kp + (size_t)r * QKVW + c);
                kk.x = f2tf32(kk.x); kk.y = f2tf32(kk.y);
                kk.z = f2tf32(kk.z); kk.w = f2tf32(kk.w);
                *(float4*)(Ks + r * KSTR + c) = kk;
                float4 vv = *(const float4*)(vp + (size_t)r * QKVW + c);
                vv.x = f2tf32(vv.x); vv.y = f2tf32(vv.y);
                vv.z = f2tf32(vv.z); vv.w = f2tf32(vv.w);
                *(float4*)(Vs + r * VSTR + c) = vv;
            }
        }
        __syncthreads();

        if (j * ABKV <= rowg0 + 15) {      // warp has unmasked work
            // ---- S = Q @ K^T ----
            float sA[8][4];
#pragma unroll
            for (int ni = 0; ni < 8; ni++)
#pragma unroll
                for (int r = 0; r < 4; r++) sA[ni][r] = 0.f;

#pragma unroll
            for (int kc = 0; kc < 8; kc++) {   // 16-float d-window per kc
                uint32_t a0[4], a1[4];
                ldsm4(a0[0], a0[1], a0[2], a0[3], qA + kc * 64);
                ldsm4(a1[0], a1[1], a1[2], a1[3], qA + kc * 64 + 32);
#pragma unroll
                for (int ni = 0; ni < 8; ni++) {
                    uint32_t b[4];
                    ldsm4(b[0], b[1], b[2], b[3],
                          kB + ni * 8 * KSTR * 4 + kc * 64);
                    mma_tf32(sA[ni], a0[0], a0[1], a0[2], a0[3], b[0], b[1]);
                    mma_tf32(sA[ni], a1[0], a1[1], a1[2], a1[3], b[2], b[3]);
                }
            }

            // ---- causal mask ----
            if (j * ABKV + ABKV - 1 > rowg0) {
                int rg = rowg0 + (lane >> 2);
#pragma unroll
                for (int ni = 0; ni < 8; ni++) {
                    int c0 = j * ABKV + ni * 8 + (lane & 3) * 2;
                    if (c0     > rg)     sA[ni][0] = -INFINITY;
                    if (c0 + 1 > rg)     sA[ni][1] = -INFINITY;
                    if (c0     > rg + 8) sA[ni][2] = -INFINITY;
                    if (c0 + 1 > rg + 8) sA[ni][3] = -INFINITY;
                }
            }

            // ---- online softmax (base 2) ----
            float mx0 = -INFINITY, mx1 = -INFINITY;
#pragma unroll
            for (int ni = 0; ni < 8; ni++) {
                mx0 = fmaxf(mx0, fmaxf(sA[ni][0], sA[ni][1]));
                mx1 = fmaxf(mx1, fmaxf(sA[ni][2], sA[ni][3]));
            }
            mx0 = fmaxf(mx0, __shfl_xor_sync(0xffffffffu, mx0, 1));
            mx0 = fmaxf(mx0, __shfl_xor_sync(0xffffffffu, mx0, 2));
            mx1 = fmaxf(mx1, __shfl_xor_sync(0xffffffffu, mx1, 1));
            mx1 = fmaxf(mx1, __shfl_xor_sync(0xffffffffu, mx1, 2));

            float mn0 = fmaxf(m0, mx0), mn1 = fmaxf(m1, mx1);
            float cr0 = exp2f(m0 - mn0), cr1 = exp2f(m1 - mn1);
            m0 = mn0; m1 = mn1;

            float s0 = 0.f, s1 = 0.f;
#pragma unroll
            for (int ni = 0; ni < 8; ni++) {
                float p0 = exp2f(sA[ni][0] - mn0);
                float p1 = exp2f(sA[ni][1] - mn0);
                float p2 = exp2f(sA[ni][2] - mn1);
                float p3 = exp2f(sA[ni][3] - mn1);
                s0 += p0 + p1;
                s1 += p2 + p3;
                sA[ni][0] = f2tf32(p0); sA[ni][1] = f2tf32(p1);
                sA[ni][2] = f2tf32(p2); sA[ni][3] = f2tf32(p3);
            }
            s0 += __shfl_xor_sync(0xffffffffu, s0, 1);
            s0 += __shfl_xor_sync(0xffffffffu, s0, 2);
            s1 += __shfl_xor_sync(0xffffffffu, s1, 1);
            s1 += __shfl_xor_sync(0xffffffffu, s1, 2);
            l0 = l0 * cr0 + s0;
            l1 = l1 * cr1 + s1;
#pragma unroll
            for (int ni = 0; ni < 16; ni++) {
                o[ni][0] *= cr0; o[ni][1] *= cr0;
                o[ni][2] *= cr1; o[ni][3] *= cr1;
            }

            // ---- stage P in warp-private smem strip ----
            {
                int rq = q0 + (lane >> 2);
                float* pr0 = &Ps[rq * PSTR + (lane & 3) * 2];
                float* pr1 = &Ps[(rq + 8) * PSTR + (lane & 3) * 2];
#pragma unroll
                for (int ni = 0; ni < 8; ni++) {
                    *(float2*)(pr0 + ni * 8) = make_float2(sA[ni][0], sA[ni][1]);
                    *(float2*)(pr1 + ni * 8) = make_float2(sA[ni][2], sA[ni][3]);
                }
            }
            __syncwarp();

            // ---- O += P @ V ----
#pragma unroll
            for (int sk = 0; sk < 8; sk++) {
                uint32_t a[4];
                ldsm4(a[0], a[1], a[2], a[3], pA + sk * 32);
                const float* vb = &Vs[(sk * 8 + (lane & 3)) * VSTR + (lane >> 2)];
#pragma unroll
                for (int ni = 0; ni < 16; ni++) {
                    uint32_t b0 = __float_as_uint(vb[ni * 8]);
                    uint32_t b1 = __float_as_uint(vb[4 * VSTR + ni * 8]);
                    mma_tf32(o[ni], a[0], a[1], a[2], a[3], b0, b1);
                }
            }
            __syncwarp();
        }
    }

    // ---- normalize + write ----
    float i0 = 1.f / l0, i1 = 1.f / l1;
    int rg = qb * ABQ + q0 + (lane >> 2);
    float* op = out + (size_t)rg * QSIZE + h * HD + (lane & 3) * 2;
#pragma unroll
    for (int ni = 0; ni < 16; ni++) {
        *(float2*)(op + ni * 8) =
            make_float2(o[ni][0] * i0, o[ni][1] * i0);
        *(float2*)(op + (size_t)8 * QSIZE + ni * 8) =
            make_float2(o[ni][2] * i1, o[ni][3] * i1);
    }
}

// ---------------------------------------------------------------------------
extern "C" void kernel_launch(void* const* d_in, const int* in_sizes, int n_in,
                              void* d_out, int out_size) {
    const int*   positions = (const int*)d_in[0];
    const float* hidden    = (const float*)d_in[1];
    const float* w_qkv     = (const float*)d_in[2];
    const float* w_o       = (const float*)d_in[3];
    float*       out       = (float*)d_out;

    void *qkv_p, *attn_p;
    cudaGetSymbolAddress(&qkv_p, g_qkv);
    cudaGetSymbolAddress(&attn_p, g_attn);
    float* qkv  = (float*)qkv_p;
    float* attn = (float*)attn_p;

    cudaFuncSetAttribute(attn_tc, cudaFuncAttributeMaxDynamicSharedMemorySize,
                         ATT_SMEM);

    // 1) qkv = hidden @ w_qkv  (tf32 TC)
    {
        dim3 grid(QKVW / BN, TT / BM);
        tgemm<<<grid, 256>>>(hidden, w_qkv, qkv, TT, QKVW, HH);
    }
    // 2) RoPE (fp32)
    {
        int total = TT * (NHEAD + NKVH) * 64;
        rope_kernel<<<(total + 255) / 256, 256>>>(positions, qkv);
    }
    // 3) attention (tf32 TC flash)
    {
        dim3 grid(NHEAD, TT / ABQ);
        attn_tc<<<grid, 256, ATT_SMEM>>>(qkv, attn);
    }
    // 4) out = attn @ w_o  (tf32 TC)
    {
        dim3 grid(HH / BN, TT / BM);
        tgemm<<<grid, 256>>>(attn, w_o, out, TT, HH, QSIZE);
    }
}

// round 4
// speedup vs baseline: 3.8639x; 1.6262x over previous
#include <cuda_runtime.h>
#include <math.h>
#include <stdint.h>

// Problem constants
#define TT    2048
#define HH    4096
#define NHEAD 32
#define NKVH  8
#define HD    128
#define QSIZE 4096          // NHEAD*HD
#define KVSIZE 1024         // NKVH*HD
#define QKVW  6144          // QSIZE + 2*KVSIZE

// Scratch (no cudaMalloc allowed)
__device__ float g_qkv[(size_t)TT * QKVW];     // 50 MB
__device__ float g_attn[(size_t)TT * QSIZE];   // 32 MB
__device__ float g_hid[(size_t)TT * HH];       // 34 MB  (tf32-rounded hidden)
__device__ float g_wqkv[(size_t)HH * QKVW];    // 101 MB (tf32-rounded w_qkv)
__device__ float g_wo[(size_t)QSIZE * HH];     // 67 MB  (tf32-rounded w_o)

// ---------------------------------------------------------------------------
// Common helpers
// ---------------------------------------------------------------------------
__device__ __forceinline__ float f2tf32(float x) {
    uint32_t u;
    asm("cvt.rna.tf32.f32 %0, %1;" : "=r"(u) : "f"(x));
    return __uint_as_float(u);
}

__device__ __forceinline__ uint32_t smem_u32(const void* p) {
    return (uint32_t)__cvta_generic_to_shared(p);
}

__device__ __forceinline__ void ldsm4(uint32_t& r0, uint32_t& r1, uint32_t& r2,
                                      uint32_t& r3, uint32_t addr) {
    asm volatile("ldmatrix.sync.aligned.m8n8.x4.shared.b16 {%0,%1,%2,%3}, [%4];"
                 : "=r"(r0), "=r"(r1), "=r"(r2), "=r"(r3) : "r"(addr));
}

__device__ __forceinline__ void mma_tf32(float c[4], uint32_t a0, uint32_t a1,
                                         uint32_t a2, uint32_t a3,
                                         uint32_t b0, uint32_t b1) {
    asm volatile(
        "mma.sync.aligned.m16n8k8.row.col.f32.tf32.tf32.f32 "
        "{%0,%1,%2,%3}, {%4,%5,%6,%7}, {%8,%9}, {%0,%1,%2,%3};"
        : "+f"(c[0]), "+f"(c[1]), "+f"(c[2]), "+f"(c[3])
        : "r"(a0), "r"(a1), "r"(a2), "r"(a3), "r"(b0), "r"(b1));
}

__device__ __forceinline__ void cpasync16(uint32_t dst, const void* src) {
    asm volatile("cp.async.cg.shared.global [%0], [%1], 16;"
                 :: "r"(dst), "l"(src));
}

// ---------------------------------------------------------------------------
// Elementwise rna-tf32 rounding pass (inputs pre-rounded so GEMM can cp.async
// raw bits with identical numerics to converting in-kernel).
// ---------------------------------------------------------------------------
__global__ void round_tf32(const float* __restrict__ in, float* __restrict__ out,
                           int n4) {
    int i = blockIdx.x * blockDim.x + threadIdx.x;
    if (i >= n4) return;
    float4 v = ((const float4*)in)[i];
    v.x = f2tf32(v.x); v.y = f2tf32(v.y);
    v.z = f2tf32(v.z); v.w = f2tf32(v.w);
    ((float4*)out)[i] = v;
}

// ---------------------------------------------------------------------------
// TF32 tensor-core GEMM, cp.async 3-stage pipeline.
// C[M,N] = A[M,K] @ B[K,N], row-major; A,B pre-rounded to tf32.
// 128x128x16 CTA tile, 8 warps (2x4), warp tile 64x32.
// A smem [m][k] stride 20 (ldmatrix, conflict-free);
// B smem [k][n] stride 136 (vector fill; direct-LDS fragments, conflict-free).
// ---------------------------------------------------------------------------
#define BM 128
#define BN 128
#define BKK 16
#define ASTR 20
#define BSTR 136
#define STAGE_A (BM * ASTR)            // floats per A stage
#define STAGE_B (BKK * BSTR)           // floats per B stage
#define TG_SMEM ((STAGE_A + STAGE_B) * 3 * 4)

__global__ __launch_bounds__(256) void tgemm(const float* __restrict__ A,
                                             const float* __restrict__ B,
                                             float* __restrict__ C,
                                             int M, int N, int K) {
    extern __shared__ float smp[];
    float* As = smp;                     // [3][BM][ASTR]
    float* Bs = smp + 3 * STAGE_A;       // [3][BKK][BSTR]

    const int tid  = threadIdx.x;
    const int lane = tid & 31;
    const int wid  = tid >> 5;
    const int mwarp = (wid >> 2) * 64;
    const int nwarp = (wid & 3) * 32;
    const int bx = blockIdx.x, by = blockIdx.y;

    // cp.async mapping: A -> thread (row=tid/2, koff=(tid&1)*8), two 16B chunks
    //                   B -> thread (k=tid/16, n=(tid%16)*8),   two 16B chunks
    const int arow = tid >> 1;
    const int akoff = (tid & 1) * 8;
    const float* Ag = A + (size_t)(by * BM + arow) * K + akoff;
    const uint32_t aDst = smem_u32(&As[arow * ASTR + akoff]);

    const int bk = tid >> 4;
    const int bn = (tid & 15) * 8;
    const float* Bg = B + (size_t)bk * N + bx * BN + bn;
    const uint32_t bDst = smem_u32(&Bs[bk * BSTR + bn]);

    const int KT = K / BKK;

#define ISSUE(kt, s)                                                    \
    {                                                                   \
        const float* a_ = Ag + (kt) * BKK;                              \
        uint32_t ad_ = aDst + (s) * (STAGE_A * 4);                      \
        cpasync16(ad_, a_);                                             \
        cpasync16(ad_ + 16, a_ + 4);                                    \
        const float* b_ = Bg + (size_t)(kt) * BKK * N;                  \
        uint32_t bd_ = bDst + (s) * (STAGE_B * 4);                      \
        cpasync16(bd_, b_);                                             \
        cpasync16(bd_ + 16, b_ + 4);                                    \
    }

    ISSUE(0, 0);
    asm volatile("cp.async.commit_group;");
    ISSUE(1, 1);
    asm volatile("cp.async.commit_group;");

    float acc[4][4][4];
#pragma unroll
    for (int mi = 0; mi < 4; mi++)
#pragma unroll
        for (int ni = 0; ni < 4; ni++)
#pragma unroll
            for (int r = 0; r < 4; r++) acc[mi][ni][r] = 0.f;

    const uint32_t aFrag0 =
        smem_u32(As) + ((mwarp + (lane & 15)) * ASTR + (lane >> 4) * 4) * 4;
    const float* bFrag0 = Bs + (lane & 3) * BSTR + nwarp + (lane >> 2);

    for (int kt = 0; kt < KT; kt++) {
        asm volatile("cp.async.wait_group 1;");
        __syncthreads();
        if (kt + 2 < KT) ISSUE(kt + 2, (kt + 2) % 3);
        asm volatile("cp.async.commit_group;");

        const int s = kt % 3;
        const uint32_t aS = aFrag0 + s * (STAGE_A * 4);
        const float* bS = bFrag0 + s * STAGE_B;

#pragma unroll
        for (int ks = 0; ks < 2; ks++) {
            uint32_t aF[4][4];
#pragma unroll
            for (int mi = 0; mi < 4; mi++)
                ldsm4(aF[mi][0], aF[mi][1], aF[mi][2], aF[mi][3],
                      aS + mi * 16 * ASTR * 4 + ks * 32);
            const float* bRow = bS + ks * 8 * BSTR;
#pragma unroll
            for (int ni = 0; ni < 4; ni++) {
                uint32_t b0 = __float_as_uint(bRow[ni * 8]);
                uint32_t b1 = __float_as_uint(bRow[4 * BSTR + ni * 8]);
#pragma unroll
                for (int mi = 0; mi < 4; mi++)
                    mma_tf32(acc[mi][ni], aF[mi][0], aF[mi][1], aF[mi][2],
                             aF[mi][3], b0, b1);
            }
        }
    }

#pragma unroll
    for (int mi = 0; mi < 4; mi++) {
#pragma unroll
        for (int ni = 0; ni < 4; ni++) {
            int r = by * BM + mwarp + mi * 16 + (lane >> 2);
            int c = bx * BN + nwarp + ni * 8 + (lane & 3) * 2;
            *(float2*)&C[(size_t)r * N + c] =
                make_float2(acc[mi][ni][0], acc[mi][ni][1]);
            *(float2*)&C[(size_t)(r + 8) * N + c] =
                make_float2(acc[mi][ni][2], acc[mi][ni][3]);
        }
    }
#undef ISSUE
}

// ---------------------------------------------------------------------------
// RoPE in-place, fp32 math
// ---------------------------------------------------------------------------
__global__ void rope_kernel(const int* __restrict__ pos, float* __restrict__ qkv) {
    const int total = TT * (NHEAD + NKVH) * 64;
    int idx = blockIdx.x * blockDim.x + threadIdx.x;
    if (idx >= total) return;
    int i = idx & 63;
    int h = (idx >> 6) % (NHEAD + NKVH);
    int t = idx / ((NHEAD + NKVH) * 64);
    int col = (h < NHEAD) ? h * HD : QSIZE + (h - NHEAD) * HD;
    float* p = qkv + (size_t)t * QKVW + col + i;
    float inv = exp2f(-(float)i * 0.2958057710522857f);
    float fr = (float)pos[t] * inv;
    float s, c;
    sincosf(fr, &s, &c);
    float x1 = p[0], x2 = p[64];
    p[0]  = x1 * c - x2 * s;
    p[64] = x2 * c + x1 * s;
}

// ---------------------------------------------------------------------------
// Tensor-core flash attention (tf32), causal, GQA group=4. (R3, epilogue now
// rounds output to tf32 so the O-projection GEMM needs no A conversion.)
// ---------------------------------------------------------------------------
#define ABQ  128
#define ABKV 64
#define QSTR 132
#define KSTR 132
#define VSTR 136
#define PSTR 68
#define ATT_SMEM ((ABQ * QSTR + ABKV * KSTR + ABKV * VSTR + ABQ * PSTR) * 4)

__global__ __launch_bounds__(256) void attn_tc(const float* __restrict__ qkv,
                                               float* __restrict__ out) {
    extern __shared__ float sm[];
    float* Qs = sm;                       // [128][QSTR]
    float* Ks = Qs + ABQ * QSTR;          // [64][KSTR]
    float* Vs = Ks + ABKV * KSTR;         // [64][VSTR]
    float* Ps = Vs + ABKV * VSTR;         // [128][PSTR]

    const int h  = blockIdx.x;
    const int qb = gridDim.y - 1 - blockIdx.y;   // heavy tiles first
    const int kvh = h >> 2;
    const int tid = threadIdx.x;
    const int lane = tid & 31;
    const int wid = tid >> 5;
    const int q0 = wid * 16;
    const float qsc = 0.08838834764831845f * 1.4426950408889634f;

    {
        const float* qp = qkv + (size_t)(qb * ABQ) * QKVW + h * HD;
        for (int i = tid; i < ABQ * 32; i += 256) {
            int r = i >> 5, c = (i & 31) * 4;
            float4 v = *(const float4*)(qp + (size_t)r * QKVW + c);
            v.x = f2tf32(v.x * qsc); v.y = f2tf32(v.y * qsc);
            v.z = f2tf32(v.z * qsc); v.w = f2tf32(v.w * qsc);
            *(float4*)(Qs + r * QSTR + c) = v;
        }
    }

    float m0 = -1e30f, m1 = -1e30f, l0 = 0.f, l1 = 0.f;
    float o[16][4];
#pragma unroll
    for (int ni = 0; ni < 16; ni++)
#pragma unroll
        for (int r = 0; r < 4; r++) o[ni][r] = 0.f;

    const uint32_t qA = smem_u32(&Qs[(q0 + (lane & 15)) * QSTR + (lane >> 4) * 4]);
    const uint32_t kB = smem_u32(&Ks[(lane & 7) * KSTR + (lane >> 3) * 4]);
    const uint32_t pA = smem_u32(&Ps[(q0 + (lane & 15)) * PSTR + (lane >> 4) * 4]);

    const int rowg0 = qb * ABQ + q0;
    const int jmax = qb * 2 + 1;

    for (int j = 0; j <= jmax; j++) {
        __syncthreads();
        {
            const float* kp = qkv + (size_t)(j * ABKV) * QKVW + QSIZE + kvh * HD;
            const float* vp = kp + KVSIZE;
            for (int i = tid; i < ABKV * 32; i += 256) {
                int r = i >> 5, c = (i & 31) * 4;
                float4 kk = *(const float4*)(kp + (size_t)r * QKVW + c);
                kk.x = f2tf32(kk.x); kk.y = f2tf32(kk.y);
                kk.z = f2tf32(kk.z); kk.w = f2tf32(kk.w);
                *(float4*)(Ks + r * KSTR + c) = kk;
                float4 vv = *(const float4*)(vp + (size_t)r * QKVW + c);
                vv.x = f2tf32(vv.x); vv.y = f2tf32(vv.y);
                vv.z = f2tf32(vv.z); vv.w = f2tf32(vv.w);
                *(float4*)(Vs + r * VSTR + c) = vv;
            }
        }
        __syncthreads();

        if (j * ABKV <= rowg0 + 15) {
            float sA[8][4];
#pragma unroll
            for (int ni = 0; ni < 8; ni++)
#pragma unroll
                for (int r = 0; r < 4; r++) sA[ni][r] = 0.f;

#pragma unroll
            for (int kc = 0; kc < 8; kc++) {
                uint32_t a0[4], a1[4];
                ldsm4(a0[0], a0[1], a0[2], a0[3], qA + kc * 64);
                ldsm4(a1[0], a1[1], a1[2], a1[3], qA + kc * 64 + 32);
#pragma unroll
                for (int ni = 0; ni < 8; ni++) {
                    uint32_t b[4];
                    ldsm4(b[0], b[1], b[2], b[3],
                          kB + ni * 8 * KSTR * 4 + kc * 64);
                    mma_tf32(sA[ni], a0[0], a0[1], a0[2], a0[3], b[0], b[1]);
                    mma_tf32(sA[ni], a1[0], a1[1], a1[2], a1[3], b[2], b[3]);
                }
            }

            if (j * ABKV + ABKV - 1 > rowg0) {
                int rg = rowg0 + (lane >> 2);
#pragma unroll
                for (int ni = 0; ni < 8; ni++) {
                    int c0 = j * ABKV + ni * 8 + (lane & 3) * 2;
                    if (c0     > rg)     sA[ni][0] = -INFINITY;
                    if (c0 + 1 > rg)     sA[ni][1] = -INFINITY;
                    if (c0     > rg + 8) sA[ni][2] = -INFINITY;
                    if (c0 + 1 > rg + 8) sA[ni][3] = -INFINITY;
                }
            }

            float mx0 = -INFINITY, mx1 = -INFINITY;
#pragma unroll
            for (int ni = 0; ni < 8; ni++) {
                mx0 = fmaxf(mx0, fmaxf(sA[ni][0], sA[ni][1]));
                mx1 = fmaxf(mx1, fmaxf(sA[ni][2], sA[ni][3]));
            }
            mx0 = fmaxf(mx0, __shfl_xor_sync(0xffffffffu, mx0, 1));
            mx0 = fmaxf(mx0, __shfl_xor_sync(0xffffffffu, mx0, 2));
            mx1 = fmaxf(mx1, __shfl_xor_sync(0xffffffffu, mx1, 1));
            mx1 = fmaxf(mx1, __shfl_xor_sync(0xffffffffu, mx1, 2));

            float mn0 = fmaxf(m0, mx0), mn1 = fmaxf(m1, mx1);
            float cr0 = exp2f(m0 - mn0), cr1 = exp2f(m1 - mn1);
            m0 = mn0; m1 = mn1;

            float s0 = 0.f, s1 = 0.f;
#pragma unroll
            for (int ni = 0; ni < 8; ni++) {
                float p0 = exp2f(sA[ni][0] - mn0);
                float p1 = exp2f(sA[ni][1] - mn0);
                float p2 = exp2f(sA[ni][2] - mn1);
                float p3 = exp2f(sA[ni][3] - mn1);
                s0 += p0 + p1;
                s1 += p2 + p3;
                sA[ni][0] = f2tf32(p0); sA[ni][1] = f2tf32(p1);
                sA[ni][2] = f2tf32(p2); sA[ni][3] = f2tf32(p3);
            }
            s0 += __shfl_xor_sync(0xffffffffu, s0, 1);
            s0 += __shfl_xor_sync(0xffffffffu, s0, 2);
            s1 += __shfl_xor_sync(0xffffffffu, s1, 1);
            s1 += __shfl_xor_sync(0xffffffffu, s1, 2);
            l0 = l0 * cr0 + s0;
            l1 = l1 * cr1 + s1;
#pragma unroll
            for (int ni = 0; ni < 16; ni++) {
                o[ni][0] *= cr0; o[ni][1] *= cr0;
                o[ni][2] *= cr1; o[ni][3] *= cr1;
            }

            {
                int rq = q0 + (lane >> 2);
                float* pr0 = &Ps[rq * PSTR + (lane & 3) * 2];
                float* pr1 = &Ps[(rq + 8) * PSTR + (lane & 3) * 2];
#pragma unroll
                for (int ni = 0; ni < 8; ni++) {
                    *(float2*)(pr0 + ni * 8) = make_float2(sA[ni][0], sA[ni][1]);
                    *(float2*)(pr1 + ni * 8) = make_float2(sA[ni][2], sA[ni][3]);
                }
            }
            __syncwarp();

#pragma unroll
            for (int sk = 0; sk < 8; sk++) {
                uint32_t a[4];
                ldsm4(a[0], a[1], a[2], a[3], pA + sk * 32);
                const float* vb = &Vs[(sk * 8 + (lane & 3)) * VSTR + (lane >> 2)];
#pragma unroll
                for (int ni = 0; ni < 16; ni++) {
                    uint32_t b0 = __float_as_uint(vb[ni * 8]);
                    uint32_t b1 = __float_as_uint(vb[4 * VSTR + ni * 8]);
                    mma_tf32(o[ni], a[0], a[1], a[2], a[3], b0, b1);
                }
            }
            __syncwarp();
        }
    }

    // normalize, round to tf32 (feeds GEMM2 A-side), write
    float i0 = 1.f / l0, i1 = 1.f / l1;
    int rg = qb * ABQ + q0 + (lane >> 2);
    float* op = out + (size_t)rg * QSIZE + h * HD + (lane & 3) * 2;
#pragma unroll
    for (int ni = 0; ni < 16; ni++) {
        *(float2*)(op + ni * 8) =
            make_float2(f2tf32(o[ni][0] * i0), f2tf32(o[ni][1] * i0));
        *(float2*)(op + (size_t)8 * QSIZE + ni * 8) =
            make_float2(f2tf32(o[ni][2] * i1), f2tf32(o[ni][3] * i1));
    }
}

// ---------------------------------------------------------------------------
extern "C" void kernel_launch(void* const* d_in, const int* in_sizes, int n_in,
                              void* d_out, int out_size) {
    const int*   positions = (const int*)d_in[0];
    const float* hidden    = (const float*)d_in[1];
    const float* w_qkv     = (const float*)d_in[2];
    const float* w_o       = (const float*)d_in[3];
    float*       out       = (float*)d_out;

    void *qkv_p, *attn_p, *hid_p, *wqkv_p, *wo_p;
    cudaGetSymbolAddress(&qkv_p, g_qkv);
    cudaGetSymbolAddress(&attn_p, g_attn);
    cudaGetSymbolAddress(&hid_p, g_hid);
    cudaGetSymbolAddress(&wqkv_p, g_wqkv);
    cudaGetSymbolAddress(&wo_p, g_wo);
    float* qkv  = (float*)qkv_p;
    float* attn = (float*)attn_p;
    float* hid  = (float*)hid_p;
    float* wqkv = (float*)wqkv_p;
    float* wo   = (float*)wo_p;

    cudaFuncSetAttribute(attn_tc, cudaFuncAttributeMaxDynamicSharedMemorySize,
                         ATT_SMEM);
    cudaFuncSetAttribute(tgemm, cudaFuncAttributeMaxDynamicSharedMemorySize,
                         TG_SMEM);

    // 0) pre-round operands to tf32 (rna), same numerics as in-kernel cvt
    {
        int n4;
        n4 = TT * HH / 4;
        round_tf32<<<(n4 + 255) / 256, 256>>>(hidden, hid, n4);
        n4 = HH * QKVW / 4;
        round_tf32<<<(n4 + 255) / 256, 256>>>(w_qkv, wqkv, n4);
        n4 = QSIZE * HH / 4;
        round_tf32<<<(n4 + 255) / 256, 256>>>(w_o, wo, n4);
    }
    // 1) qkv = hid @ wqkv
    {
        dim3 grid(QKVW / BN, TT / BM);
        tgemm<<<grid, 256, TG_SMEM>>>(hid, wqkv, qkv, TT, QKVW, HH);
    }
    // 2) RoPE
    {
        int total = TT * (NHEAD + NKVH) * 64;
        rope_kernel<<<(total + 255) / 256, 256>>>(positions, qkv);
    }
    // 3) attention
    {
        dim3 grid(NHEAD, TT / ABQ);
        attn_tc<<<grid, 256, ATT_SMEM>>>(qkv, attn);
    }
    // 4) out = attn @ wo
    {
        dim3 grid(HH / BN, TT / BM);
        tgemm<<<grid, 256, TG_SMEM>>>(attn, wo, out, TT, HH, QSIZE);
    }
}